// round 5
// baseline (speedup 1.0000x reference)
#include <cuda_runtime.h>
#include <cstdint>

#define B 16
#define H0 720
#define W0 720
#define HP 359
#define WP 359
#define H2 357
#define W2 357
#define H3 355
#define W3 355

#define W1P 368
#define W2P 368
#define W3P 360

__device__ __align__(128) float g_p1[B * 10 * HP * W1P];
__device__ __align__(128) float g_p2[B * 16 * H2 * W2P];
__device__ __align__(128) float g_p3[B * 32 * H3 * W3P];

typedef unsigned long long ull;

__device__ __forceinline__ ull pack2(float a, float b) {
    ull r;
    asm("mov.b64 %0, {%1,%2};" : "=l"(r) : "f"(a), "f"(b));
    return r;
}
__device__ __forceinline__ void fma2(ull& d, ull a, ull b) {
    asm("fma.rn.f32x2 %0, %1, %2, %0;" : "+l"(d) : "l"(a), "l"(b));
}
__device__ __forceinline__ float2 unpack2(ull v) {
    float2 f;
    asm("mov.b64 {%0,%1}, %2;" : "=f"(f.x), "=f"(f.y) : "l"(v));
    return f;
}
__device__ __forceinline__ float to_tf32(float f) {
    uint32_t u;
    asm("cvt.rna.tf32.f32 %0, %1;" : "=r"(u) : "f"(f));
    return __uint_as_float(u);
}
__device__ __forceinline__ void mma_tf32(float d[4],
                                         uint32_t a0, uint32_t a1, uint32_t a2, uint32_t a3,
                                         uint32_t b0, uint32_t b1) {
    asm("mma.sync.aligned.m16n8k8.row.col.f32.tf32.tf32.f32 "
        "{%0,%1,%2,%3}, {%4,%5,%6,%7}, {%8,%9}, {%0,%1,%2,%3};"
        : "+f"(d[0]), "+f"(d[1]), "+f"(d[2]), "+f"(d[3])
        : "r"(a0), "r"(a1), "r"(a2), "r"(a3), "r"(b0), "r"(b1));
}

// =====================================================================
// Kernel 1: conv1(3->10,3x3)+PReLU+maxpool, norm folded. (unchanged path,
// outputs rounded to tf32 for the mma consumer)
// =====================================================================
__global__ __launch_bounds__(64)
void k_conv1_pool(const float* __restrict__ x,
                  const float* __restrict__ w,
                  const float* __restrict__ bias,
                  const float* __restrict__ alpha)
{
    __shared__ ull   s_wd[135];
    __shared__ float s_b2[5];
    __shared__ float s_a2[5];

    int cg = blockIdx.z & 1;
    int b  = blockIdx.z >> 1;

    for (int i = threadIdx.x; i < 135; i += blockDim.x) {
        float wv = w[cg * 135 + i] * 0.0078125f;
        s_wd[i] = pack2(wv, wv);
    }
    if (threadIdx.x < 5) {
        int co = cg * 5 + threadIdx.x;
        float s = 0.f;
#pragma unroll
        for (int k = 0; k < 27; k++) s += w[co * 27 + k];
        s_b2[threadIdx.x] = bias[co] - 127.5f * 0.0078125f * s;
        s_a2[threadIdx.x] = alpha[co];
    }
    __syncthreads();

    int t = blockIdx.x * blockDim.x + threadIdx.x;
    if (t >= 180) return;
    int py = blockIdx.y;
    int iy = 2 * py;
    int x4 = 4 * t;

    ull acc[5][2][2];
#pragma unroll
    for (int co = 0; co < 5; co++) {
        float bb = s_b2[co];
        ull bp = pack2(bb, bb);
        acc[co][0][0] = bp; acc[co][0][1] = bp;
        acc[co][1][0] = bp; acc[co][1][1] = bp;
    }

#pragma unroll
    for (int ci = 0; ci < 3; ci++) {
        const float* rp = x + ((size_t)(b * 3 + ci) * H0 + iy) * W0 + x4;
        ull pr[4][5];
#pragma unroll
        for (int r = 0; r < 4; r++) {
            float4 v4 = *(const float4*)(rp + (size_t)r * W0);
            float2 v2 = make_float2(0.f, 0.f);
            if (t < 179) v2 = *(const float2*)(rp + (size_t)r * W0 + 4);
            pr[r][0] = pack2(v4.x, v4.y);
            pr[r][1] = pack2(v4.y, v4.z);
            pr[r][2] = pack2(v4.z, v4.w);
            pr[r][3] = pack2(v4.w, v2.x);
            pr[r][4] = pack2(v2.x, v2.y);
        }
#pragma unroll
        for (int co = 0; co < 5; co++) {
#pragma unroll
            for (int ky = 0; ky < 3; ky++)
#pragma unroll
                for (int kx = 0; kx < 3; kx++) {
                    ull wd = s_wd[co * 27 + ci * 9 + ky * 3 + kx];
                    fma2(acc[co][0][0], pr[ky    ][kx    ], wd);
                    fma2(acc[co][0][1], pr[ky    ][kx + 2], wd);
                    fma2(acc[co][1][0], pr[ky + 1][kx    ], wd);
                    fma2(acc[co][1][1], pr[ky + 1][kx + 2], wd);
                }
        }
    }

#pragma unroll
    for (int co = 0; co < 5; co++) {
        float a = s_a2[co];
        float2 r00 = unpack2(acc[co][0][0]);
        float2 r01 = unpack2(acc[co][0][1]);
        float2 r10 = unpack2(acc[co][1][0]);
        float2 r11 = unpack2(acc[co][1][1]);
        float p00 = r00.x >= 0.f ? r00.x : a * r00.x;
        float p01 = r00.y >= 0.f ? r00.y : a * r00.y;
        float p10 = r10.x >= 0.f ? r10.x : a * r10.x;
        float p11 = r10.y >= 0.f ? r10.y : a * r10.y;
        float q00 = r01.x >= 0.f ? r01.x : a * r01.x;
        float q01 = r01.y >= 0.f ? r01.y : a * r01.y;
        float q10 = r11.x >= 0.f ? r11.x : a * r11.x;
        float q11 = r11.y >= 0.f ? r11.y : a * r11.y;
        float m0 = fmaxf(fmaxf(p00, p01), fmaxf(p10, p11));
        float m1 = fmaxf(fmaxf(q00, q01), fmaxf(q10, q11));
        float* op = g_p1 + ((size_t)(b * 10 + cg * 5 + co) * HP + py) * W1P + 2 * t;
        *(float2*)op = make_float2(to_tf32(m0), to_tf32(m1));
    }
}

// =====================================================================
// Kernel 2: conv2 (10->16,3x3)+PReLU via tf32 mma.sync
// CTA(128): one output row y, 128 x, all 16 couts. K padded 10->16 ci.
// =====================================================================
__global__ __launch_bounds__(128)
void k_conv2_mma(const float* __restrict__ w,
                 const float* __restrict__ bias,
                 const float* __restrict__ alpha)
{
    __shared__ float  s_in[3 * 132 * 18];   // [ky][x][slot]
    __shared__ float2 s_B[72 * 17];         // [(s*4+t)][co]
    __shared__ float  s_bias[16];
    __shared__ float  s_alpha[16];

    int tid = threadIdx.x;
    int b  = blockIdx.z;
    int y  = blockIdx.y;
    int x0 = blockIdx.x * 128;

    for (int e = tid; e < 72 * 16; e += 128) {
        int co = e & 15; int rest = e >> 4;
        int t4 = rest & 3; int s = rest >> 2;
        int h = s & 1, o = s >> 1;
        int ky = o / 3, kx = o - 3 * (o / 3);
        int ci0 = h * 8 + t4, ci1 = ci0 + 4;
        float f0 = (ci0 < 10) ? w[((co * 10 + ci0) * 3 + ky) * 3 + kx] : 0.f;
        float f1 = (ci1 < 10) ? w[((co * 10 + ci1) * 3 + ky) * 3 + kx] : 0.f;
        s_B[(s * 4 + t4) * 17 + co] = make_float2(to_tf32(f0), to_tf32(f1));
    }
    if (tid < 16) { s_bias[tid] = bias[tid]; s_alpha[tid] = alpha[tid]; }

    for (int e = tid; e < 3 * 16 * 132; e += 128) {
        int xx = e % 132; int rest = e / 132;
        int ci = rest & 15; int ky = rest >> 4;
        float v = 0.f;
        int gx = x0 + xx;
        if (ci < 10 && gx < W1P)
            v = g_p1[((size_t)(b * 10 + ci) * HP + (y + ky)) * W1P + gx];
        int slot = ((ci >> 3) << 3) + ((ci & 3) << 1) + ((ci >> 2) & 1);
        s_in[(ky * 132 + xx) * 18 + slot] = v;
    }
    __syncthreads();

    int warp = tid >> 5, lane = tid & 31;
    int g = lane >> 2, t = lane & 3;
    int xw = warp * 32;

    float D[2][2][4] = {};

#pragma unroll
    for (int s = 0; s < 18; s++) {
        const int h = s & 1, o = s >> 1;
        const int ky = o / 3, kx = o - 3 * (o / 3);
        uint32_t bb[2][2];
#pragma unroll
        for (int nt = 0; nt < 2; nt++) {
            float2 bf = s_B[(s * 4 + t) * 17 + nt * 8 + g];
            bb[nt][0] = __float_as_uint(bf.x);
            bb[nt][1] = __float_as_uint(bf.y);
        }
#pragma unroll
        for (int mt = 0; mt < 2; mt++) {
            int xl = xw + mt * 16 + g + kx;
            const float* ap = &s_in[(ky * 132 + xl) * 18 + h * 8 + t * 2];
            float2 lo = *(const float2*)ap;
            float2 hi = *(const float2*)(ap + 8 * 18);
            uint32_t a0 = __float_as_uint(lo.x), a1 = __float_as_uint(hi.x);
            uint32_t a2 = __float_as_uint(lo.y), a3 = __float_as_uint(hi.y);
#pragma unroll
            for (int nt = 0; nt < 2; nt++)
                mma_tf32(D[mt][nt], a0, a1, a2, a3, bb[nt][0], bb[nt][1]);
        }
    }

    __syncthreads();
    float* s_out = s_in;   // reuse: 16*132 floats
#pragma unroll
    for (int mt = 0; mt < 2; mt++)
#pragma unroll
        for (int nt = 0; nt < 2; nt++) {
            int co0 = nt * 8 + 2 * t, co1 = co0 + 1;
            int xr0 = xw + mt * 16 + g, xr1 = xr0 + 8;
            float b0v = s_bias[co0], b1v = s_bias[co1];
            float a0v = s_alpha[co0], a1v = s_alpha[co1];
            float v;
            v = D[mt][nt][0] + b0v; v = v >= 0.f ? v : a0v * v; s_out[co0 * 132 + xr0] = to_tf32(v);
            v = D[mt][nt][1] + b1v; v = v >= 0.f ? v : a1v * v; s_out[co1 * 132 + xr0] = to_tf32(v);
            v = D[mt][nt][2] + b0v; v = v >= 0.f ? v : a0v * v; s_out[co0 * 132 + xr1] = to_tf32(v);
            v = D[mt][nt][3] + b1v; v = v >= 0.f ? v : a1v * v; s_out[co1 * 132 + xr1] = to_tf32(v);
        }
    __syncthreads();

    for (int f = tid; f < 16 * 32; f += 128) {
        int co = f >> 5, xq = f & 31;
        int gx = x0 + xq * 4;
        if (gx < 357) {
            float4 v = *(const float4*)&s_out[co * 132 + xq * 4];
            *(float4*)&g_p2[((size_t)(b * 16 + co) * H2 + y) * W2P + gx] = v;
        }
    }
}

// =====================================================================
// Kernel 3: conv3 (16->32,3x3)+PReLU via tf32 mma.sync
// CTA(128): one output row y, 128 x, all 32 couts. K = 16ci x 9 = 18 ksteps.
// =====================================================================
__global__ __launch_bounds__(128)
void k_conv3_mma(const float* __restrict__ w,
                 const float* __restrict__ bias,
                 const float* __restrict__ alpha)
{
    __shared__ float  s_in[3 * 132 * 18];   // 28512 B
    __shared__ float2 s_B[72 * 33];         // 19008 B
    __shared__ float  s_bias[32];
    __shared__ float  s_alpha[32];

    int tid = threadIdx.x;
    int b  = blockIdx.z;
    int y  = blockIdx.y;
    int x0 = blockIdx.x * 128;

    for (int e = tid; e < 72 * 32; e += 128) {
        int co = e & 31; int rest = e >> 5;
        int t4 = rest & 3; int s = rest >> 2;
        int h = s & 1, o = s >> 1;
        int ky = o / 3, kx = o - 3 * (o / 3);
        int ci0 = h * 8 + t4, ci1 = ci0 + 4;
        float f0 = w[((co * 16 + ci0) * 3 + ky) * 3 + kx];
        float f1 = w[((co * 16 + ci1) * 3 + ky) * 3 + kx];
        s_B[(s * 4 + t4) * 33 + co] = make_float2(to_tf32(f0), to_tf32(f1));
    }
    if (tid < 32) { s_bias[tid] = bias[tid]; s_alpha[tid] = alpha[tid]; }

    for (int e = tid; e < 3 * 16 * 132; e += 128) {
        int xx = e % 132; int rest = e / 132;
        int ci = rest & 15; int ky = rest >> 4;
        float v = 0.f;
        int gx = x0 + xx;
        if (gx < W2P)
            v = g_p2[((size_t)(b * 16 + ci) * H2 + (y + ky)) * W2P + gx];
        int slot = ((ci >> 3) << 3) + ((ci & 3) << 1) + ((ci >> 2) & 1);
        s_in[(ky * 132 + xx) * 18 + slot] = v;
    }
    __syncthreads();

    int warp = tid >> 5, lane = tid & 31;
    int g = lane >> 2, t = lane & 3;
    int xw = warp * 32;

    float D[2][4][4] = {};

#pragma unroll
    for (int s = 0; s < 18; s++) {
        const int h = s & 1, o = s >> 1;
        const int ky = o / 3, kx = o - 3 * (o / 3);
        uint32_t bb[4][2];
#pragma unroll
        for (int nt = 0; nt < 4; nt++) {
            float2 bf = s_B[(s * 4 + t) * 33 + nt * 8 + g];
            bb[nt][0] = __float_as_uint(bf.x);
            bb[nt][1] = __float_as_uint(bf.y);
        }
#pragma unroll
        for (int mt = 0; mt < 2; mt++) {
            int xl = xw + mt * 16 + g + kx;
            const float* ap = &s_in[(ky * 132 + xl) * 18 + h * 8 + t * 2];
            float2 lo = *(const float2*)ap;
            float2 hi = *(const float2*)(ap + 8 * 18);
            uint32_t a0 = __float_as_uint(lo.x), a1 = __float_as_uint(hi.x);
            uint32_t a2 = __float_as_uint(lo.y), a3 = __float_as_uint(hi.y);
#pragma unroll
            for (int nt = 0; nt < 4; nt++)
                mma_tf32(D[mt][nt], a0, a1, a2, a3, bb[nt][0], bb[nt][1]);
        }
    }

    __syncthreads();
    float* s_out = s_in;   // reuse: 32*132 = 4224 floats
#pragma unroll
    for (int mt = 0; mt < 2; mt++)
#pragma unroll
        for (int nt = 0; nt < 4; nt++) {
            int co0 = nt * 8 + 2 * t, co1 = co0 + 1;
            int xr0 = xw + mt * 16 + g, xr1 = xr0 + 8;
            float b0v = s_bias[co0], b1v = s_bias[co1];
            float a0v = s_alpha[co0], a1v = s_alpha[co1];
            float v;
            v = D[mt][nt][0] + b0v; v = v >= 0.f ? v : a0v * v; s_out[co0 * 132 + xr0] = v;
            v = D[mt][nt][1] + b1v; v = v >= 0.f ? v : a1v * v; s_out[co1 * 132 + xr0] = v;
            v = D[mt][nt][2] + b0v; v = v >= 0.f ? v : a0v * v; s_out[co0 * 132 + xr1] = v;
            v = D[mt][nt][3] + b1v; v = v >= 0.f ? v : a1v * v; s_out[co1 * 132 + xr1] = v;
        }
    __syncthreads();

    for (int f = tid; f < 32 * 32; f += 128) {
        int co = f >> 5, xq = f & 31;
        int gx = x0 + xq * 4;
        if (gx < 357) {
            float4 v = *(const float4*)&s_out[co * 132 + xq * 4];
            *(float4*)&g_p3[((size_t)(b * 32 + co) * H3 + y) * W3P + gx] = v;
        }
    }
}

// =====================================================================
// Kernel 4: 1x1 heads + softmax (unchanged)
// =====================================================================
__global__ __launch_bounds__(96)
void k_heads(const float* __restrict__ w41,
             const float* __restrict__ b41,
             const float* __restrict__ w42,
             const float* __restrict__ b42,
             float* __restrict__ out)
{
    __shared__ ull s41d[64];
    __shared__ ull s42d[128];
    __shared__ float sb41[2];
    __shared__ float sb42[4];
    for (int i = threadIdx.x; i < 64; i += blockDim.x) s41d[i] = pack2(w41[i], w41[i]);
    for (int i = threadIdx.x; i < 128; i += blockDim.x) s42d[i] = pack2(w42[i], w42[i]);
    if (threadIdx.x < 2) sb41[threadIdx.x] = b41[threadIdx.x];
    if (threadIdx.x < 4) sb42[threadIdx.x] = b42[threadIdx.x];
    __syncthreads();

    int t = threadIdx.x;
    if (t >= 89) return;
    int x0 = 4 * t;
    int py = blockIdx.y;
    int b  = blockIdx.z;

    const float* p = g_p3 + ((size_t)(b * 32) * H3 + py) * W3P + x0;

    ull l0a, l0b, l1a, l1b;
    ull r0a, r0b, r1a, r1b, r2a, r2b, r3a, r3b;
    {
        float v = sb41[0]; l0a = pack2(v, v); l0b = l0a;
        v = sb41[1]; l1a = pack2(v, v); l1b = l1a;
        v = sb42[0]; r0a = pack2(v, v); r0b = r0a;
        v = sb42[1]; r1a = pack2(v, v); r1b = r1a;
        v = sb42[2]; r2a = pack2(v, v); r2b = r2a;
        v = sb42[3]; r3a = pack2(v, v); r3b = r3a;
    }

#pragma unroll
    for (int ci = 0; ci < 32; ci++) {
        float4 v4 = *(const float4*)(p + (size_t)ci * H3 * W3P);
        ull va = pack2(v4.x, v4.y);
        ull vb = pack2(v4.z, v4.w);
        ull w;
        w = s41d[ci];       fma2(l0a, va, w); fma2(l0b, vb, w);
        w = s41d[32 + ci];  fma2(l1a, va, w); fma2(l1b, vb, w);
        w = s42d[ci];       fma2(r0a, va, w); fma2(r0b, vb, w);
        w = s42d[32 + ci];  fma2(r1a, va, w); fma2(r1b, vb, w);
        w = s42d[64 + ci];  fma2(r2a, va, w); fma2(r2b, vb, w);
        w = s42d[96 + ci];  fma2(r3a, va, w); fma2(r3b, vb, w);
    }

    float2 L0[2] = {unpack2(l0a), unpack2(l0b)};
    float2 L1[2] = {unpack2(l1a), unpack2(l1b)};
    float2 R0[2] = {unpack2(r0a), unpack2(r0b)};
    float2 R1[2] = {unpack2(r1a), unpack2(r1b)};
    float2 R2[2] = {unpack2(r2a), unpack2(r2b)};
    float2 R3[2] = {unpack2(r3a), unpack2(r3b)};

    const size_t plane = (size_t)H3 * W3;
    const size_t PROB_OFF = (size_t)B * 4 * plane;
    size_t pixbase = (size_t)py * W3 + x0;

#pragma unroll
    for (int j = 0; j < 4; j++) {
        int xx = x0 + j;
        if (xx >= W3) break;
        int h = j >> 1;
        float l0 = (j & 1) ? L0[h].y : L0[h].x;
        float l1 = (j & 1) ? L1[h].y : L1[h].x;
        float v0 = (j & 1) ? R0[h].y : R0[h].x;
        float v1 = (j & 1) ? R1[h].y : R1[h].x;
        float v2 = (j & 1) ? R2[h].y : R2[h].x;
        float v3 = (j & 1) ? R3[h].y : R3[h].x;
        float m = fmaxf(l0, l1);
        float e0 = __expf(l0 - m), e1 = __expf(l1 - m);
        float inv = 1.0f / (e0 + e1);
        size_t pix = pixbase + j;
        out[((size_t)(b * 4 + 0)) * plane + pix] = v0;
        out[((size_t)(b * 4 + 1)) * plane + pix] = v1;
        out[((size_t)(b * 4 + 2)) * plane + pix] = v2;
        out[((size_t)(b * 4 + 3)) * plane + pix] = v3;
        out[PROB_OFF + ((size_t)(b * 2 + 0)) * plane + pix] = e0 * inv;
        out[PROB_OFF + ((size_t)(b * 2 + 1)) * plane + pix] = e1 * inv;
    }
}

extern "C" void kernel_launch(void* const* d_in, const int* in_sizes, int n_in,
                              void* d_out, int out_size)
{
    const float* x        = (const float*)d_in[0];
    const float* conv1_w  = (const float*)d_in[1];
    const float* conv1_b  = (const float*)d_in[2];
    const float* prelu1_a = (const float*)d_in[3];
    const float* conv2_w  = (const float*)d_in[4];
    const float* conv2_b  = (const float*)d_in[5];
    const float* prelu2_a = (const float*)d_in[6];
    const float* conv3_w  = (const float*)d_in[7];
    const float* conv3_b  = (const float*)d_in[8];
    const float* prelu3_a = (const float*)d_in[9];
    const float* conv41_w = (const float*)d_in[10];
    const float* conv41_b = (const float*)d_in[11];
    const float* conv42_w = (const float*)d_in[12];
    const float* conv42_b = (const float*)d_in[13];
    float* out = (float*)d_out;

    dim3 g1(3, HP, B * 2);
    k_conv1_pool<<<g1, 64>>>(x, conv1_w, conv1_b, prelu1_a);

    dim3 g2(3, H2, B);
    k_conv2_mma<<<g2, 128>>>(conv2_w, conv2_b, prelu2_a);

    dim3 g3(3, H3, B);
    k_conv3_mma<<<g3, 128>>>(conv3_w, conv3_b, prelu3_a);

    dim3 g4(1, H3, B);
    k_heads<<<g4, 96>>>(conv41_w, conv41_b, conv42_w, conv42_b, out);
}

// round 6
// speedup vs baseline: 1.5864x; 1.5864x over previous
#include <cuda_runtime.h>
#include <cstdint>

#define B 16
#define H0 720
#define W0 720
#define HP 359
#define WP 359
#define H2 357
#define W2 357
#define H3 355
#define W3 355

#define W1P 368
#define W2P 368

__device__ __align__(128) float g_p1[B * 10 * HP * W1P];
__device__ __align__(128) float g_p2[B * 16 * H2 * W2P];

// prepacked tf32 B-fragment images (exact smem layout)
__device__ __align__(16) float2 g_w2B[72 * 17];
__device__ __align__(16) float2 g_w3B[72 * 33];

typedef unsigned long long ull;

__device__ __forceinline__ ull pack2(float a, float b) {
    ull r;
    asm("mov.b64 %0, {%1,%2};" : "=l"(r) : "f"(a), "f"(b));
    return r;
}
__device__ __forceinline__ void fma2(ull& d, ull a, ull b) {
    asm("fma.rn.f32x2 %0, %1, %2, %0;" : "+l"(d) : "l"(a), "l"(b));
}
__device__ __forceinline__ float2 unpack2(ull v) {
    float2 f;
    asm("mov.b64 {%0,%1}, %2;" : "=f"(f.x), "=f"(f.y) : "l"(v));
    return f;
}
__device__ __forceinline__ float to_tf32(float f) {
    uint32_t u;
    asm("cvt.rna.tf32.f32 %0, %1;" : "=r"(u) : "f"(f));
    return __uint_as_float(u);
}
__device__ __forceinline__ void mma_tf32(float d[4],
                                         uint32_t a0, uint32_t a1, uint32_t a2, uint32_t a3,
                                         uint32_t b0, uint32_t b1) {
    asm("mma.sync.aligned.m16n8k8.row.col.f32.tf32.tf32.f32 "
        "{%0,%1,%2,%3}, {%4,%5,%6,%7}, {%8,%9}, {%0,%1,%2,%3};"
        : "+f"(d[0]), "+f"(d[1]), "+f"(d[2]), "+f"(d[3])
        : "r"(a0), "r"(a1), "r"(a2), "r"(a3), "r"(b0), "r"(b1));
}

// =====================================================================
// Prep: pack conv2/conv3 weights into B-fragment images (run once/launch)
// =====================================================================
__global__ void k_prep(const float* __restrict__ w2, const float* __restrict__ w3)
{
    int e = blockIdx.x * blockDim.x + threadIdx.x;
    if (e < 72 * 17) {
        int row = e / 17, co = e - row * 17;
        int s = row >> 2, t = row & 3;
        int h = s & 1, o = s >> 1;
        int ky = o / 3, kx = o - 3 * (o / 3);
        float f0 = 0.f, f1 = 0.f;
        if (co < 16) {
            int ci0 = h * 8 + t, ci1 = ci0 + 4;
            if (ci0 < 10) f0 = w2[((co * 10 + ci0) * 3 + ky) * 3 + kx];
            if (ci1 < 10) f1 = w2[((co * 10 + ci1) * 3 + ky) * 3 + kx];
        }
        g_w2B[e] = make_float2(to_tf32(f0), to_tf32(f1));
    }
    if (e < 72 * 33) {
        int row = e / 33, co = e - row * 33;
        int s = row >> 2, t = row & 3;
        int h = s & 1, o = s >> 1;
        int ky = o / 3, kx = o - 3 * (o / 3);
        float f0 = 0.f, f1 = 0.f;
        if (co < 32) {
            int ci0 = h * 8 + t, ci1 = ci0 + 4;
            f0 = w3[((co * 16 + ci0) * 3 + ky) * 3 + kx];
            f1 = w3[((co * 16 + ci1) * 3 + ky) * 3 + kx];
        }
        g_w3B[e] = make_float2(to_tf32(f0), to_tf32(f1));
    }
}

// =====================================================================
// Kernel 1: conv1(3->10,3x3)+PReLU+maxpool, norm folded (unchanged)
// =====================================================================
__global__ __launch_bounds__(64)
void k_conv1_pool(const float* __restrict__ x,
                  const float* __restrict__ w,
                  const float* __restrict__ bias,
                  const float* __restrict__ alpha)
{
    __shared__ ull   s_wd[135];
    __shared__ float s_b2[5];
    __shared__ float s_a2[5];

    int cg = blockIdx.z & 1;
    int b  = blockIdx.z >> 1;

    for (int i = threadIdx.x; i < 135; i += blockDim.x) {
        float wv = w[cg * 135 + i] * 0.0078125f;
        s_wd[i] = pack2(wv, wv);
    }
    if (threadIdx.x < 5) {
        int co = cg * 5 + threadIdx.x;
        float s = 0.f;
#pragma unroll
        for (int k = 0; k < 27; k++) s += w[co * 27 + k];
        s_b2[threadIdx.x] = bias[co] - 127.5f * 0.0078125f * s;
        s_a2[threadIdx.x] = alpha[co];
    }
    __syncthreads();

    int t = blockIdx.x * blockDim.x + threadIdx.x;
    if (t >= 180) return;
    int py = blockIdx.y;
    int iy = 2 * py;
    int x4 = 4 * t;

    ull acc[5][2][2];
#pragma unroll
    for (int co = 0; co < 5; co++) {
        float bb = s_b2[co];
        ull bp = pack2(bb, bb);
        acc[co][0][0] = bp; acc[co][0][1] = bp;
        acc[co][1][0] = bp; acc[co][1][1] = bp;
    }

#pragma unroll
    for (int ci = 0; ci < 3; ci++) {
        const float* rp = x + ((size_t)(b * 3 + ci) * H0 + iy) * W0 + x4;
        ull pr[4][5];
#pragma unroll
        for (int r = 0; r < 4; r++) {
            float4 v4 = *(const float4*)(rp + (size_t)r * W0);
            float2 v2 = make_float2(0.f, 0.f);
            if (t < 179) v2 = *(const float2*)(rp + (size_t)r * W0 + 4);
            pr[r][0] = pack2(v4.x, v4.y);
            pr[r][1] = pack2(v4.y, v4.z);
            pr[r][2] = pack2(v4.z, v4.w);
            pr[r][3] = pack2(v4.w, v2.x);
            pr[r][4] = pack2(v2.x, v2.y);
        }
#pragma unroll
        for (int co = 0; co < 5; co++) {
#pragma unroll
            for (int ky = 0; ky < 3; ky++)
#pragma unroll
                for (int kx = 0; kx < 3; kx++) {
                    ull wd = s_wd[co * 27 + ci * 9 + ky * 3 + kx];
                    fma2(acc[co][0][0], pr[ky    ][kx], wd);
                    fma2(acc[co][0][1], pr[ky    ][kx + 2], wd);
                    fma2(acc[co][1][0], pr[ky + 1][kx], wd);
                    fma2(acc[co][1][1], pr[ky + 1][kx + 2], wd);
                }
        }
    }

#pragma unroll
    for (int co = 0; co < 5; co++) {
        float a = s_a2[co];
        float2 r00 = unpack2(acc[co][0][0]);
        float2 r01 = unpack2(acc[co][0][1]);
        float2 r10 = unpack2(acc[co][1][0]);
        float2 r11 = unpack2(acc[co][1][1]);
        float p00 = r00.x >= 0.f ? r00.x : a * r00.x;
        float p01 = r00.y >= 0.f ? r00.y : a * r00.y;
        float p10 = r10.x >= 0.f ? r10.x : a * r10.x;
        float p11 = r10.y >= 0.f ? r10.y : a * r10.y;
        float q00 = r01.x >= 0.f ? r01.x : a * r01.x;
        float q01 = r01.y >= 0.f ? r01.y : a * r01.y;
        float q10 = r11.x >= 0.f ? r11.x : a * r11.x;
        float q11 = r11.y >= 0.f ? r11.y : a * r11.y;
        float m0 = fmaxf(fmaxf(p00, p01), fmaxf(p10, p11));
        float m1 = fmaxf(fmaxf(q00, q01), fmaxf(q10, q11));
        float* op = g_p1 + ((size_t)(b * 10 + cg * 5 + co) * HP + py) * W1P + 2 * t;
        *(float2*)op = make_float2(to_tf32(m0), to_tf32(m1));
    }
}

// =====================================================================
// Kernel 2: conv2 (10->16,3x3)+PReLU via tf32 mma, R=8 rows/CTA
// smem: s_in [16][10][140] floats + s_B image + bias/alpha
// =====================================================================
#define SMEM2 (89600 + 9792 + 128)
__global__ __launch_bounds__(128)
void k_conv2_mma(const float* __restrict__ bias,
                 const float* __restrict__ alpha)
{
    extern __shared__ char smem[];
    float*  s_in   = (float*)smem;                    // 16*1400
    float2* s_B    = (float2*)(smem + 89600);         // 72*17
    float*  s_bias = (float*)(smem + 89600 + 9792);   // 16
    float*  s_alpha = s_bias + 16;

    int tid = threadIdx.x;
    int b   = blockIdx.z;
    int y0  = blockIdx.y * 8;
    int x0  = blockIdx.x * 128;

    {
        const float4* src = (const float4*)g_w2B;
        float4* dst = (float4*)s_B;
        for (int i = tid; i < 612; i += 128) dst[i] = src[i];
    }
    if (tid < 16) { s_bias[tid] = bias[tid]; s_alpha[tid] = alpha[tid]; }

    for (int i = tid; i < 16 * 10 * 33; i += 128) {
        int ci  = i / 330;
        int rem = i - ci * 330;
        int r   = rem / 33;
        int xq  = rem - r * 33;
        int gx  = x0 + xq * 4;
        int grow = y0 + r; if (grow > HP - 1) grow = HP - 1;
        float4 v = make_float4(0.f, 0.f, 0.f, 0.f);
        if (ci < 10 && gx < W1P)
            v = *(const float4*)&g_p1[((size_t)(b * 10 + ci) * HP + grow) * W1P + gx];
        *(float4*)&s_in[ci * 1400 + r * 140 + xq * 4] = v;
    }
    __syncthreads();

    int warp = tid >> 5, lane = tid & 31;
    int g = lane >> 2, t = lane & 3;
    int xw = warp * 32;

    // per-lane bias/alpha regs
    float bval[2][2], aval[2][2];
#pragma unroll
    for (int nt = 0; nt < 2; nt++)
#pragma unroll
        for (int c = 0; c < 2; c++) {
            int co = nt * 8 + 2 * t + c;
            bval[nt][c] = s_bias[co];
            aval[nt][c] = s_alpha[co];
        }

    for (int r = 0; r < 8; r++) {
        int y = y0 + r;
        if (y >= H2) break;
        float D[2][2][4] = {};
#pragma unroll
        for (int s = 0; s < 18; s++) {
            int h = s & 1, o = s >> 1;
            int ky = o / 3, kx = o - 3 * (o / 3);
            uint32_t bb[2][2];
#pragma unroll
            for (int nt = 0; nt < 2; nt++) {
                float2 bf = s_B[(s * 4 + t) * 17 + nt * 8 + g];
                bb[nt][0] = __float_as_uint(bf.x);
                bb[nt][1] = __float_as_uint(bf.y);
            }
#pragma unroll
            for (int mt = 0; mt < 2; mt++) {
                const float* ap = &s_in[(h * 8 + t) * 1400 + (r + ky) * 140 + xw + mt * 16 + kx + g];
                uint32_t a0 = __float_as_uint(ap[0]);
                uint32_t a1 = __float_as_uint(ap[8]);
                uint32_t a2 = __float_as_uint(ap[4 * 1400]);
                uint32_t a3 = __float_as_uint(ap[4 * 1400 + 8]);
#pragma unroll
                for (int nt = 0; nt < 2; nt++)
                    mma_tf32(D[mt][nt], a0, a1, a2, a3, bb[nt][0], bb[nt][1]);
            }
        }
        // epilogue: bias + PReLU + tf32 round, direct stores
#pragma unroll
        for (int mt = 0; mt < 2; mt++) {
            int xlo = x0 + xw + mt * 16 + g;
#pragma unroll
            for (int nt = 0; nt < 2; nt++) {
#pragma unroll
                for (int c = 0; c < 2; c++) {
                    int co = nt * 8 + 2 * t + c;
                    float* op = &g_p2[((size_t)(b * 16 + co) * H2 + y) * W2P];
                    float v0 = D[mt][nt][c]     + bval[nt][c];
                    float v1 = D[mt][nt][c + 2] + bval[nt][c];
                    v0 = v0 >= 0.f ? v0 : aval[nt][c] * v0;
                    v1 = v1 >= 0.f ? v1 : aval[nt][c] * v1;
                    if (xlo < W2)     op[xlo]     = to_tf32(v0);
                    if (xlo + 8 < W2) op[xlo + 8] = to_tf32(v1);
                }
            }
        }
    }
}

// =====================================================================
// Kernel 3: conv3 (16->32,3x3)+PReLU + fused 1x1 heads + softmax
// writes d_out directly: [reg(16,4,355,355), prob(16,2,355,355)]
// =====================================================================
#define SMEM3 (89600 + 19008 + 256)
__global__ __launch_bounds__(128)
void k_conv3_heads(const float* __restrict__ bias,
                   const float* __restrict__ alpha,
                   const float* __restrict__ w41,
                   const float* __restrict__ b41,
                   const float* __restrict__ w42,
                   const float* __restrict__ b42,
                   float* __restrict__ out)
{
    extern __shared__ char smem[];
    float*  s_in   = (float*)smem;                     // 16*1400
    float2* s_B    = (float2*)(smem + 89600);          // 72*33
    float*  s_bias = (float*)(smem + 89600 + 19008);   // 32
    float*  s_alpha = s_bias + 32;

    int tid = threadIdx.x;
    int b   = blockIdx.z;
    int y0  = blockIdx.y * 8;
    int x0  = blockIdx.x * 128;

    {
        const float4* src = (const float4*)g_w3B;
        float4* dst = (float4*)s_B;
        for (int i = tid; i < 1188; i += 128) dst[i] = src[i];
    }
    if (tid < 32) { s_bias[tid] = bias[tid]; s_alpha[tid] = alpha[tid]; }

    for (int i = tid; i < 16 * 10 * 33; i += 128) {
        int ci  = i / 330;
        int rem = i - ci * 330;
        int r   = rem / 33;
        int xq  = rem - r * 33;
        int gx  = x0 + xq * 4;
        int grow = y0 + r; if (grow > H2 - 1) grow = H2 - 1;
        float4 v = make_float4(0.f, 0.f, 0.f, 0.f);
        if (gx < W2P)
            v = *(const float4*)&g_p2[((size_t)(b * 16 + ci) * H2 + grow) * W2P + gx];
        *(float4*)&s_in[ci * 1400 + r * 140 + xq * 4] = v;
    }
    __syncthreads();

    int warp = tid >> 5, lane = tid & 31;
    int g = lane >> 2, t = lane & 3;
    int xw = warp * 32;

    // per-lane conv3 bias/alpha + head weights (regs)
    float bval[4][2], aval[4][2];
    float wh[4][2][6];
#pragma unroll
    for (int nt = 0; nt < 4; nt++)
#pragma unroll
        for (int c = 0; c < 2; c++) {
            int co = nt * 8 + 2 * t + c;
            bval[nt][c] = s_bias[co];
            aval[nt][c] = s_alpha[co];
            wh[nt][c][0] = w41[co];
            wh[nt][c][1] = w41[32 + co];
            wh[nt][c][2] = w42[co];
            wh[nt][c][3] = w42[32 + co];
            wh[nt][c][4] = w42[64 + co];
            wh[nt][c][5] = w42[96 + co];
        }
    float hb0 = b41[0], hb1 = b41[1];
    float hb2 = b42[0], hb3 = b42[1], hb4 = b42[2], hb5 = b42[3];

    const size_t plane = (size_t)H3 * W3;
    const size_t PROB_OFF = (size_t)B * 4 * plane;

    for (int r = 0; r < 8; r++) {
        int y = y0 + r;
        if (y >= H3) break;
        float D[2][4][4] = {};
#pragma unroll
        for (int s = 0; s < 18; s++) {
            int h = s & 1, o = s >> 1;
            int ky = o / 3, kx = o - 3 * (o / 3);
            uint32_t bb[4][2];
#pragma unroll
            for (int nt = 0; nt < 4; nt++) {
                float2 bf = s_B[(s * 4 + t) * 33 + nt * 8 + g];
                bb[nt][0] = __float_as_uint(bf.x);
                bb[nt][1] = __float_as_uint(bf.y);
            }
#pragma unroll
            for (int mt = 0; mt < 2; mt++) {
                const float* ap = &s_in[(h * 8 + t) * 1400 + (r + ky) * 140 + xw + mt * 16 + kx + g];
                uint32_t a0 = __float_as_uint(ap[0]);
                uint32_t a1 = __float_as_uint(ap[8]);
                uint32_t a2 = __float_as_uint(ap[4 * 1400]);
                uint32_t a3 = __float_as_uint(ap[4 * 1400 + 8]);
#pragma unroll
                for (int nt = 0; nt < 4; nt++)
                    mma_tf32(D[mt][nt], a0, a1, a2, a3, bb[nt][0], bb[nt][1]);
            }
        }

        // fused epilogue: PReLU + 1x1 heads (quad-reduce) + softmax
        size_t rowbase = (size_t)y * W3;
#pragma unroll
        for (int mt = 0; mt < 2; mt++) {
#pragma unroll
            for (int p = 0; p < 2; p++) {
                float a0s = 0.f, a1s = 0.f, a2s = 0.f, a3s = 0.f, a4s = 0.f, a5s = 0.f;
#pragma unroll
                for (int nt = 0; nt < 4; nt++) {
#pragma unroll
                    for (int c = 0; c < 2; c++) {
                        float v = D[mt][nt][2 * p + c] + bval[nt][c];
                        v = v >= 0.f ? v : aval[nt][c] * v;
                        a0s += wh[nt][c][0] * v;
                        a1s += wh[nt][c][1] * v;
                        a2s += wh[nt][c][2] * v;
                        a3s += wh[nt][c][3] * v;
                        a4s += wh[nt][c][4] * v;
                        a5s += wh[nt][c][5] * v;
                    }
                }
                // quad reduction (lanes t=0..3 share pixel)
                a0s += __shfl_xor_sync(0xffffffff, a0s, 1);
                a1s += __shfl_xor_sync(0xffffffff, a1s, 1);
                a2s += __shfl_xor_sync(0xffffffff, a2s, 1);
                a3s += __shfl_xor_sync(0xffffffff, a3s, 1);
                a4s += __shfl_xor_sync(0xffffffff, a4s, 1);
                a5s += __shfl_xor_sync(0xffffffff, a5s, 1);
                a0s += __shfl_xor_sync(0xffffffff, a0s, 2);
                a1s += __shfl_xor_sync(0xffffffff, a1s, 2);
                a2s += __shfl_xor_sync(0xffffffff, a2s, 2);
                a3s += __shfl_xor_sync(0xffffffff, a3s, 2);
                a4s += __shfl_xor_sync(0xffffffff, a4s, 2);
                a5s += __shfl_xor_sync(0xffffffff, a5s, 2);

                int x = x0 + xw + mt * 16 + g + 8 * p;
                if (x < W3) {
                    size_t pix = rowbase + x;
                    // lane t stores reg channel t; lane 0 also stores probs
                    float rv = (t == 0 ? a2s + hb2 : t == 1 ? a3s + hb3 :
                                t == 2 ? a4s + hb4 : a5s + hb5);
                    out[((size_t)(b * 4 + t)) * plane + pix] = rv;
                    if (t == 0) {
                        float l0 = a0s + hb0, l1 = a1s + hb1;
                        float m = fmaxf(l0, l1);
                        float e0 = __expf(l0 - m), e1 = __expf(l1 - m);
                        float inv = 1.0f / (e0 + e1);
                        out[PROB_OFF + ((size_t)(b * 2 + 0)) * plane + pix] = e0 * inv;
                        out[PROB_OFF + ((size_t)(b * 2 + 1)) * plane + pix] = e1 * inv;
                    }
                }
            }
        }
    }
}

extern "C" void kernel_launch(void* const* d_in, const int* in_sizes, int n_in,
                              void* d_out, int out_size)
{
    const float* x        = (const float*)d_in[0];
    const float* conv1_w  = (const float*)d_in[1];
    const float* conv1_b  = (const float*)d_in[2];
    const float* prelu1_a = (const float*)d_in[3];
    const float* conv2_w  = (const float*)d_in[4];
    const float* conv2_b  = (const float*)d_in[5];
    const float* prelu2_a = (const float*)d_in[6];
    const float* conv3_w  = (const float*)d_in[7];
    const float* conv3_b  = (const float*)d_in[8];
    const float* prelu3_a = (const float*)d_in[9];
    const float* conv41_w = (const float*)d_in[10];
    const float* conv41_b = (const float*)d_in[11];
    const float* conv42_w = (const float*)d_in[12];
    const float* conv42_b = (const float*)d_in[13];
    float* out = (float*)d_out;

    static int attr_done = 0;
    if (!attr_done) {
        cudaFuncSetAttribute(k_conv2_mma, cudaFuncAttributeMaxDynamicSharedMemorySize, SMEM2);
        cudaFuncSetAttribute(k_conv3_heads, cudaFuncAttributeMaxDynamicSharedMemorySize, SMEM3);
        attr_done = 1;
    }

    k_prep<<<10, 256>>>(conv2_w, conv3_w);

    dim3 g1(3, HP, B * 2);
    k_conv1_pool<<<g1, 64>>>(x, conv1_w, conv1_b, prelu1_a);

    dim3 g2(3, (H2 + 7) / 8, B);
    k_conv2_mma<<<g2, 128, SMEM2>>>(conv2_b, prelu2_a);

    dim3 g3(3, (H3 + 7) / 8, B);
    k_conv3_heads<<<g3, 128, SMEM3>>>(conv3_b, prelu3_a,
                                      conv41_w, conv41_b, conv42_w, conv42_b, out);
}

// round 7
// speedup vs baseline: 1.8675x; 1.1772x over previous
#include <cuda_runtime.h>
#include <cstdint>

#define B 16
#define H0 720
#define W0 720
#define HP 359
#define WP 359
#define H2 357
#define W2 357
#define H3 355
#define W3 355

#define W1P 368
#define W2P 368

__device__ __align__(128) float g_p1[B * 10 * HP * W1P];
__device__ __align__(128) float g_p2[B * 16 * H2 * W2P];

__device__ __align__(16) float2 g_w2B[72 * 17];
__device__ __align__(16) float2 g_w3B[72 * 33];

typedef unsigned long long ull;

__device__ __forceinline__ ull pack2(float a, float b) {
    ull r;
    asm("mov.b64 %0, {%1,%2};" : "=l"(r) : "f"(a), "f"(b));
    return r;
}
__device__ __forceinline__ void fma2(ull& d, ull a, ull b) {
    asm("fma.rn.f32x2 %0, %1, %2, %0;" : "+l"(d) : "l"(a), "l"(b));
}
__device__ __forceinline__ float2 unpack2(ull v) {
    float2 f;
    asm("mov.b64 {%0,%1}, %2;" : "=f"(f.x), "=f"(f.y) : "l"(v));
    return f;
}
__device__ __forceinline__ float to_tf32(float f) {
    uint32_t u;
    asm("cvt.rna.tf32.f32 %0, %1;" : "=r"(u) : "f"(f));
    return __uint_as_float(u);
}
__device__ __forceinline__ void mma_tf32(float d[4],
                                         uint32_t a0, uint32_t a1, uint32_t a2, uint32_t a3,
                                         uint32_t b0, uint32_t b1) {
    asm("mma.sync.aligned.m16n8k8.row.col.f32.tf32.tf32.f32 "
        "{%0,%1,%2,%3}, {%4,%5,%6,%7}, {%8,%9}, {%0,%1,%2,%3};"
        : "+f"(d[0]), "+f"(d[1]), "+f"(d[2]), "+f"(d[3])
        : "r"(a0), "r"(a1), "r"(a2), "r"(a3), "r"(b0), "r"(b1));
}

// =====================================================================
// Prep: pack conv2/conv3 weights into B-fragment images
// =====================================================================
__global__ void k_prep(const float* __restrict__ w2, const float* __restrict__ w3)
{
    int e = blockIdx.x * blockDim.x + threadIdx.x;
    if (e < 72 * 17) {
        int row = e / 17, co = e - row * 17;
        int s = row >> 2, t = row & 3;
        int h = s & 1, o = s >> 1;
        int ky = o / 3, kx = o - 3 * (o / 3);
        float f0 = 0.f, f1 = 0.f;
        if (co < 16) {
            int ci0 = h * 8 + t, ci1 = ci0 + 4;
            if (ci0 < 10) f0 = w2[((co * 10 + ci0) * 3 + ky) * 3 + kx];
            if (ci1 < 10) f1 = w2[((co * 10 + ci1) * 3 + ky) * 3 + kx];
        }
        g_w2B[e] = make_float2(to_tf32(f0), to_tf32(f1));
    }
    if (e < 72 * 33) {
        int row = e / 33, co = e - row * 33;
        int s = row >> 2, t = row & 3;
        int h = s & 1, o = s >> 1;
        int ky = o / 3, kx = o - 3 * (o / 3);
        float f0 = 0.f, f1 = 0.f;
        if (co < 32) {
            int ci0 = h * 8 + t, ci1 = ci0 + 4;
            f0 = w3[((co * 16 + ci0) * 3 + ky) * 3 + kx];
            f1 = w3[((co * 16 + ci1) * 3 + ky) * 3 + kx];
        }
        g_w3B[e] = make_float2(to_tf32(f0), to_tf32(f1));
    }
}

// =====================================================================
// Kernel 1: conv1(3->10,3x3)+PReLU+maxpool, norm folded (unchanged)
// =====================================================================
__global__ __launch_bounds__(64)
void k_conv1_pool(const float* __restrict__ x,
                  const float* __restrict__ w,
                  const float* __restrict__ bias,
                  const float* __restrict__ alpha)
{
    __shared__ ull   s_wd[135];
    __shared__ float s_b2[5];
    __shared__ float s_a2[5];

    int cg = blockIdx.z & 1;
    int b  = blockIdx.z >> 1;

    for (int i = threadIdx.x; i < 135; i += blockDim.x) {
        float wv = w[cg * 135 + i] * 0.0078125f;
        s_wd[i] = pack2(wv, wv);
    }
    if (threadIdx.x < 5) {
        int co = cg * 5 + threadIdx.x;
        float s = 0.f;
#pragma unroll
        for (int k = 0; k < 27; k++) s += w[co * 27 + k];
        s_b2[threadIdx.x] = bias[co] - 127.5f * 0.0078125f * s;
        s_a2[threadIdx.x] = alpha[co];
    }
    __syncthreads();

    int t = blockIdx.x * blockDim.x + threadIdx.x;
    if (t >= 180) return;
    int py = blockIdx.y;
    int iy = 2 * py;
    int x4 = 4 * t;

    ull acc[5][2][2];
#pragma unroll
    for (int co = 0; co < 5; co++) {
        float bb = s_b2[co];
        ull bp = pack2(bb, bb);
        acc[co][0][0] = bp; acc[co][0][1] = bp;
        acc[co][1][0] = bp; acc[co][1][1] = bp;
    }

#pragma unroll
    for (int ci = 0; ci < 3; ci++) {
        const float* rp = x + ((size_t)(b * 3 + ci) * H0 + iy) * W0 + x4;
        ull pr[4][5];
#pragma unroll
        for (int r = 0; r < 4; r++) {
            float4 v4 = *(const float4*)(rp + (size_t)r * W0);
            float2 v2 = make_float2(0.f, 0.f);
            if (t < 179) v2 = *(const float2*)(rp + (size_t)r * W0 + 4);
            pr[r][0] = pack2(v4.x, v4.y);
            pr[r][1] = pack2(v4.y, v4.z);
            pr[r][2] = pack2(v4.z, v4.w);
            pr[r][3] = pack2(v4.w, v2.x);
            pr[r][4] = pack2(v2.x, v2.y);
        }
#pragma unroll
        for (int co = 0; co < 5; co++) {
#pragma unroll
            for (int ky = 0; ky < 3; ky++)
#pragma unroll
                for (int kx = 0; kx < 3; kx++) {
                    ull wd = s_wd[co * 27 + ci * 9 + ky * 3 + kx];
                    fma2(acc[co][0][0], pr[ky    ][kx], wd);
                    fma2(acc[co][0][1], pr[ky    ][kx + 2], wd);
                    fma2(acc[co][1][0], pr[ky + 1][kx], wd);
                    fma2(acc[co][1][1], pr[ky + 1][kx + 2], wd);
                }
        }
    }

#pragma unroll
    for (int co = 0; co < 5; co++) {
        float a = s_a2[co];
        float2 r00 = unpack2(acc[co][0][0]);
        float2 r01 = unpack2(acc[co][0][1]);
        float2 r10 = unpack2(acc[co][1][0]);
        float2 r11 = unpack2(acc[co][1][1]);
        float p00 = r00.x >= 0.f ? r00.x : a * r00.x;
        float p01 = r00.y >= 0.f ? r00.y : a * r00.y;
        float p10 = r10.x >= 0.f ? r10.x : a * r10.x;
        float p11 = r10.y >= 0.f ? r10.y : a * r10.y;
        float q00 = r01.x >= 0.f ? r01.x : a * r01.x;
        float q01 = r01.y >= 0.f ? r01.y : a * r01.y;
        float q10 = r11.x >= 0.f ? r11.x : a * r11.x;
        float q11 = r11.y >= 0.f ? r11.y : a * r11.y;
        float m0 = fmaxf(fmaxf(p00, p01), fmaxf(p10, p11));
        float m1 = fmaxf(fmaxf(q00, q01), fmaxf(q10, q11));
        float* op = g_p1 + ((size_t)(b * 10 + cg * 5 + co) * HP + py) * W1P + 2 * t;
        *(float2*)op = make_float2(to_tf32(m0), to_tf32(m1));
    }
}

// =====================================================================
// Kernel 2: conv2 via tf32 mma, 256 thr: warps 0-3 rows 0-3, 4-7 rows 4-7
// =====================================================================
#define SMEM2 (89600 + 9792 + 128)
__global__ __launch_bounds__(256)
void k_conv2_mma(const float* __restrict__ bias,
                 const float* __restrict__ alpha)
{
    extern __shared__ char smem[];
    float*  s_in   = (float*)smem;                    // 16*1400
    float2* s_B    = (float2*)(smem + 89600);         // 72*17
    float*  s_bias = (float*)(smem + 89600 + 9792);   // 16
    float*  s_alpha = s_bias + 16;

    int tid = threadIdx.x;
    int b   = blockIdx.z;
    int y0  = blockIdx.y * 8;
    int x0  = blockIdx.x * 128;

    {
        const float4* src = (const float4*)g_w2B;
        float4* dst = (float4*)s_B;
        for (int i = tid; i < 612; i += 256) dst[i] = src[i];
    }
    if (tid < 16) { s_bias[tid] = bias[tid]; s_alpha[tid] = alpha[tid]; }

    for (int i = tid; i < 16 * 10 * 33; i += 256) {
        int ci  = i / 330;
        int rem = i - ci * 330;
        int r   = rem / 33;
        int xq  = rem - r * 33;
        int gx  = x0 + xq * 4;
        int grow = y0 + r; if (grow > HP - 1) grow = HP - 1;
        float4 v = make_float4(0.f, 0.f, 0.f, 0.f);
        if (ci < 10 && gx < W1P)
            v = *(const float4*)&g_p1[((size_t)(b * 10 + ci) * HP + grow) * W1P + gx];
        *(float4*)&s_in[ci * 1400 + r * 140 + xq * 4] = v;
    }
    __syncthreads();

    int warp = tid >> 5, lane = tid & 31;
    int warpx = warp & 3, warpr = warp >> 2;
    int g = lane >> 2, t = lane & 3;
    int xw = warpx * 32;
    int rbase = warpr * 4;

    float bval[2][2], aval[2][2];
#pragma unroll
    for (int nt = 0; nt < 2; nt++)
#pragma unroll
        for (int c = 0; c < 2; c++) {
            int co = nt * 8 + 2 * t + c;
            bval[nt][c] = s_bias[co];
            aval[nt][c] = s_alpha[co];
        }

    for (int rr = 0; rr < 4; rr++) {
        int r = rbase + rr;
        int y = y0 + r;
        if (y >= H2) break;
        float D[2][2][4] = {};
#pragma unroll
        for (int s = 0; s < 18; s++) {
            int h = s & 1, o = s >> 1;
            int ky = o / 3, kx = o - 3 * (o / 3);
            uint32_t bb[2][2];
#pragma unroll
            for (int nt = 0; nt < 2; nt++) {
                float2 bf = s_B[(s * 4 + t) * 17 + nt * 8 + g];
                bb[nt][0] = __float_as_uint(bf.x);
                bb[nt][1] = __float_as_uint(bf.y);
            }
#pragma unroll
            for (int mt = 0; mt < 2; mt++) {
                const float* ap = &s_in[(h * 8 + t) * 1400 + (r + ky) * 140 + xw + mt * 16 + kx + g];
                uint32_t a0 = __float_as_uint(ap[0]);
                uint32_t a1 = __float_as_uint(ap[8]);
                uint32_t a2 = __float_as_uint(ap[4 * 1400]);
                uint32_t a3 = __float_as_uint(ap[4 * 1400 + 8]);
#pragma unroll
                for (int nt = 0; nt < 2; nt++)
                    mma_tf32(D[mt][nt], a0, a1, a2, a3, bb[nt][0], bb[nt][1]);
            }
        }
#pragma unroll
        for (int mt = 0; mt < 2; mt++) {
            int xlo = x0 + xw + mt * 16 + g;
#pragma unroll
            for (int nt = 0; nt < 2; nt++) {
#pragma unroll
                for (int c = 0; c < 2; c++) {
                    int co = nt * 8 + 2 * t + c;
                    float* op = &g_p2[((size_t)(b * 16 + co) * H2 + y) * W2P];
                    float v0 = D[mt][nt][c]     + bval[nt][c];
                    float v1 = D[mt][nt][c + 2] + bval[nt][c];
                    v0 = v0 >= 0.f ? v0 : aval[nt][c] * v0;
                    v1 = v1 >= 0.f ? v1 : aval[nt][c] * v1;
                    if (xlo < W2)     op[xlo]     = to_tf32(v0);
                    if (xlo + 8 < W2) op[xlo + 8] = to_tf32(v1);
                }
            }
        }
    }
}

// =====================================================================
// Kernel 3: conv3+heads via tf32 mma, 256 thr (r-split), fused softmax
// =====================================================================
#define SMEM3 (89600 + 19008 + 256)
__global__ __launch_bounds__(256)
void k_conv3_heads(const float* __restrict__ bias,
                   const float* __restrict__ alpha,
                   const float* __restrict__ w41,
                   const float* __restrict__ b41,
                   const float* __restrict__ w42,
                   const float* __restrict__ b42,
                   float* __restrict__ out)
{
    extern __shared__ char smem[];
    float*  s_in   = (float*)smem;                     // 16*1400
    float2* s_B    = (float2*)(smem + 89600);          // 72*33
    float*  s_bias = (float*)(smem + 89600 + 19008);   // 32
    float*  s_alpha = s_bias + 32;

    int tid = threadIdx.x;
    int b   = blockIdx.z;
    int y0  = blockIdx.y * 8;
    int x0  = blockIdx.x * 128;

    {
        const float4* src = (const float4*)g_w3B;
        float4* dst = (float4*)s_B;
        for (int i = tid; i < 1188; i += 256) dst[i] = src[i];
    }
    if (tid < 32) { s_bias[tid] = bias[tid]; s_alpha[tid] = alpha[tid]; }

    for (int i = tid; i < 16 * 10 * 33; i += 256) {
        int ci  = i / 330;
        int rem = i - ci * 330;
        int r   = rem / 33;
        int xq  = rem - r * 33;
        int gx  = x0 + xq * 4;
        int grow = y0 + r; if (grow > H2 - 1) grow = H2 - 1;
        float4 v = make_float4(0.f, 0.f, 0.f, 0.f);
        if (gx < W2P)
            v = *(const float4*)&g_p2[((size_t)(b * 16 + ci) * H2 + grow) * W2P + gx];
        *(float4*)&s_in[ci * 1400 + r * 140 + xq * 4] = v;
    }
    __syncthreads();

    int warp = tid >> 5, lane = tid & 31;
    int warpx = warp & 3, warpr = warp >> 2;
    int g = lane >> 2, t = lane & 3;
    int xw = warpx * 32;
    int rbase = warpr * 4;

    float bval[4][2], aval[4][2];
    float wh[4][2][6];
#pragma unroll
    for (int nt = 0; nt < 4; nt++)
#pragma unroll
        for (int c = 0; c < 2; c++) {
            int co = nt * 8 + 2 * t + c;
            bval[nt][c] = s_bias[co];
            aval[nt][c] = s_alpha[co];
            wh[nt][c][0] = w41[co];
            wh[nt][c][1] = w41[32 + co];
            wh[nt][c][2] = w42[co];
            wh[nt][c][3] = w42[32 + co];
            wh[nt][c][4] = w42[64 + co];
            wh[nt][c][5] = w42[96 + co];
        }
    float hb0 = b41[0], hb1 = b41[1];
    float hb2 = b42[0], hb3 = b42[1], hb4 = b42[2], hb5 = b42[3];

    const size_t plane = (size_t)H3 * W3;
    const size_t PROB_OFF = (size_t)B * 4 * plane;

    for (int rr = 0; rr < 4; rr++) {
        int r = rbase + rr;
        int y = y0 + r;
        if (y >= H3) break;
        float D[2][4][4] = {};
#pragma unroll
        for (int s = 0; s < 18; s++) {
            int h = s & 1, o = s >> 1;
            int ky = o / 3, kx = o - 3 * (o / 3);
            uint32_t bb[4][2];
#pragma unroll
            for (int nt = 0; nt < 4; nt++) {
                float2 bf = s_B[(s * 4 + t) * 33 + nt * 8 + g];
                bb[nt][0] = __float_as_uint(bf.x);
                bb[nt][1] = __float_as_uint(bf.y);
            }
#pragma unroll
            for (int mt = 0; mt < 2; mt++) {
                const float* ap = &s_in[(h * 8 + t) * 1400 + (r + ky) * 140 + xw + mt * 16 + kx + g];
                uint32_t a0 = __float_as_uint(ap[0]);
                uint32_t a1 = __float_as_uint(ap[8]);
                uint32_t a2 = __float_as_uint(ap[4 * 1400]);
                uint32_t a3 = __float_as_uint(ap[4 * 1400 + 8]);
#pragma unroll
                for (int nt = 0; nt < 4; nt++)
                    mma_tf32(D[mt][nt], a0, a1, a2, a3, bb[nt][0], bb[nt][1]);
            }
        }

        size_t rowbase = (size_t)y * W3;
#pragma unroll
        for (int mt = 0; mt < 2; mt++) {
#pragma unroll
            for (int p = 0; p < 2; p++) {
                float a0s = 0.f, a1s = 0.f, a2s = 0.f, a3s = 0.f, a4s = 0.f, a5s = 0.f;
#pragma unroll
                for (int nt = 0; nt < 4; nt++) {
#pragma unroll
                    for (int c = 0; c < 2; c++) {
                        float v = D[mt][nt][2 * p + c] + bval[nt][c];
                        v = v >= 0.f ? v : aval[nt][c] * v;
                        a0s += wh[nt][c][0] * v;
                        a1s += wh[nt][c][1] * v;
                        a2s += wh[nt][c][2] * v;
                        a3s += wh[nt][c][3] * v;
                        a4s += wh[nt][c][4] * v;
                        a5s += wh[nt][c][5] * v;
                    }
                }
                a0s += __shfl_xor_sync(0xffffffff, a0s, 1);
                a1s += __shfl_xor_sync(0xffffffff, a1s, 1);
                a2s += __shfl_xor_sync(0xffffffff, a2s, 1);
                a3s += __shfl_xor_sync(0xffffffff, a3s, 1);
                a4s += __shfl_xor_sync(0xffffffff, a4s, 1);
                a5s += __shfl_xor_sync(0xffffffff, a5s, 1);
                a0s += __shfl_xor_sync(0xffffffff, a0s, 2);
                a1s += __shfl_xor_sync(0xffffffff, a1s, 2);
                a2s += __shfl_xor_sync(0xffffffff, a2s, 2);
                a3s += __shfl_xor_sync(0xffffffff, a3s, 2);
                a4s += __shfl_xor_sync(0xffffffff, a4s, 2);
                a5s += __shfl_xor_sync(0xffffffff, a5s, 2);

                int x = x0 + xw + mt * 16 + g + 8 * p;
                if (x < W3) {
                    size_t pix = rowbase + x;
                    float rv = (t == 0 ? a2s + hb2 : t == 1 ? a3s + hb3 :
                                t == 2 ? a4s + hb4 : a5s + hb5);
                    out[((size_t)(b * 4 + t)) * plane + pix] = rv;
                    if (t == 0) {
                        float l0 = a0s + hb0, l1 = a1s + hb1;
                        float m = fmaxf(l0, l1);
                        float e0 = __expf(l0 - m), e1 = __expf(l1 - m);
                        float inv = 1.0f / (e0 + e1);
                        out[PROB_OFF + ((size_t)(b * 2 + 0)) * plane + pix] = e0 * inv;
                        out[PROB_OFF + ((size_t)(b * 2 + 1)) * plane + pix] = e1 * inv;
                    }
                }
            }
        }
    }
}

extern "C" void kernel_launch(void* const* d_in, const int* in_sizes, int n_in,
                              void* d_out, int out_size)
{
    const float* x        = (const float*)d_in[0];
    const float* conv1_w  = (const float*)d_in[1];
    const float* conv1_b  = (const float*)d_in[2];
    const float* prelu1_a = (const float*)d_in[3];
    const float* conv2_w  = (const float*)d_in[4];
    const float* conv2_b  = (const float*)d_in[5];
    const float* prelu2_a = (const float*)d_in[6];
    const float* conv3_w  = (const float*)d_in[7];
    const float* conv3_b  = (const float*)d_in[8];
    const float* prelu3_a = (const float*)d_in[9];
    const float* conv41_w = (const float*)d_in[10];
    const float* conv41_b = (const float*)d_in[11];
    const float* conv42_w = (const float*)d_in[12];
    const float* conv42_b = (const float*)d_in[13];
    float* out = (float*)d_out;

    static int attr_done = 0;
    if (!attr_done) {
        cudaFuncSetAttribute(k_conv2_mma, cudaFuncAttributeMaxDynamicSharedMemorySize, SMEM2);
        cudaFuncSetAttribute(k_conv3_heads, cudaFuncAttributeMaxDynamicSharedMemorySize, SMEM3);
        attr_done = 1;
    }

    k_prep<<<10, 256>>>(conv2_w, conv3_w);

    dim3 g1(3, HP, B * 2);
    k_conv1_pool<<<g1, 64>>>(x, conv1_w, conv1_b, prelu1_a);

    dim3 g2(3, (H2 + 7) / 8, B);
    k_conv2_mma<<<g2, 256, SMEM2>>>(conv2_b, prelu2_a);

    dim3 g3(3, (H3 + 7) / 8, B);
    k_conv3_heads<<<g3, 256, SMEM3>>>(conv3_b, prelu3_a,
                                      conv41_w, conv41_b, conv42_w, conv42_b, out);
}